// round 13
// baseline (speedup 1.0000x reference)
#include <cuda_runtime.h>

// ---------------------------------------------------------------------------
// SpatialAttn2: B=16, L=32, N=256, P=16, H=4, F=12, HID=4, W=16
// out[B,W,F,N] | attn1[B,W,H,N,N] | attn2[B,W,N,N] | Wv1 | Wv2
// R13: R11 + packed stage-1 projections (fma2 + ulonglong2 W rows) +
//      double-buffered Qs / VT-row parity (4 fewer barriers).
//      (R12's redux.f32 rejected by ptxas on sm_103 — SHFL butterflies kept.)
// ---------------------------------------------------------------------------

#define N_   256
#define P_   16
#define H_   4
#define F_   12
#define HID_ 4
#define W_   16
#define L_   32
#define BW_  256

static const unsigned long long OFF_A1  = 786432ull;
static const unsigned long long OFF_A2  = 786432ull + 67108864ull;
static const unsigned long long OFF_WV1 = 786432ull + 67108864ull + 16777216ull;
static const unsigned long long OFF_WV2 = OFF_WV1 + 256ull;
static const long long TOT_FULL = 84672960ll;

#define QSCALE 0.36067376022224085f   // 0.25 * log2(e)

__device__ unsigned int g_maskbits[N_ * 8];

typedef unsigned long long u64;

__device__ __forceinline__ u64 pk2(float a, float b) {
    u64 r; asm("mov.b64 %0, {%1,%2};" : "=l"(r) : "f"(a), "f"(b)); return r;
}
__device__ __forceinline__ void upk2(u64 v, float& a, float& b) {
    asm("mov.b64 {%0,%1}, %2;" : "=f"(a), "=f"(b) : "l"(v));
}
__device__ __forceinline__ u64 fma2_(u64 a, u64 b, u64 c) {
    u64 d; asm("fma.rn.f32x2 %0, %1, %2, %3;" : "=l"(d) : "l"(a), "l"(b), "l"(c)); return d;
}
__device__ __forceinline__ u64 mul2_(u64 a, u64 b) {
    u64 d; asm("mul.rn.f32x2 %0, %1, %2;" : "=l"(d) : "l"(a), "l"(b)); return d;
}
__device__ __forceinline__ u64 add2_(u64 a, u64 b) {
    u64 d; asm("add.rn.f32x2 %0, %1, %2;" : "=l"(d) : "l"(a), "l"(b)); return d;
}
__device__ __forceinline__ float ex2_(float x) {
    float y; asm("ex2.approx.f32 %0, %1;" : "=f"(y) : "f"(x)); return y;
}
__device__ __forceinline__ u64 warp_sum2(u64 v) {
#pragma unroll
    for (int o = 16; o > 0; o >>= 1)
        v = add2_(v, __shfl_xor_sync(0xffffffffu, v, o));
    return v;
}

// ---------------------------------------------------------------------------
__global__ void pack_mask_kernel(const int* __restrict__ mask,
                                 const float* __restrict__ Wv1,
                                 const float* __restrict__ Wv2,
                                 float* __restrict__ out, int wW) {
    const int tid = threadIdx.x;
    const int row = blockIdx.x;
    int v = mask[row * N_ + tid];
    unsigned int bal = __ballot_sync(0xffffffffu, v > 0);
    if ((tid & 31) == 0) g_maskbits[row * 8 + (tid >> 5)] = bal;
    if (wW && row == 0) {
        out[OFF_WV1 + tid] = Wv1[tid];
        if (tid < 192) out[OFF_WV2 + tid] = Wv2[tid];
    }
}

// ---------------------------------------------------------------------------
struct __align__(16) Smem {
    float xT [P_][N_];
    float h1T[P_][N_];
    float Qs [2][N_][20];        // double-buffered query rows
    float VT [F_][N_];
    unsigned char mbL[N_][32];   // per-(row,lane) mask byte
    float Wa1[H_][P_][P_];
    float Wv1[H_][P_][HID_];
    float Wa2[P_][P_];
    float Wv2[P_][F_];
};

__global__ void __launch_bounds__(256, 2)
spatial_attn_kernel(const float* __restrict__ inp,
                    const float* __restrict__ Wa1,
                    const float* __restrict__ Wv1,
                    const float* __restrict__ Wa2,
                    const float* __restrict__ Wv2,
                    float* __restrict__ out, int wA) {
    extern __shared__ char smraw[];
    Smem& S = *reinterpret_cast<Smem*>(smraw);
    const int tid  = threadIdx.x;
    const int lane = tid & 31;
    const int wid  = tid >> 5;
    const int bw   = blockIdx.x;
    const int b    = bw >> 4;
    const int w    = bw & 15;

    // ---- stage 0: load xT, weights; build mask byte table ------------------
#pragma unroll
    for (int p = 0; p < P_; p++)
        S.xT[p][tid] = inp[(b * L_ + w + p) * N_ + tid];
#pragma unroll
    for (int j = 0; j < 8; j++) {
        int idx = tid + 256 * j;
        int r = idx >> 3, g = idx & 7;
        unsigned A = g_maskbits[r * 8 + (g >> 1)];
        unsigned B = g_maskbits[r * 8 + 4 + (g >> 1)];
        int base = (g & 1) * 16;
        unsigned wd = 0;
#pragma unroll
        for (int i2 = 0; i2 < 4; i2++) {
            unsigned byte = ((A >> (base + 4 * i2)) & 0xFu)
                          | (((B >> (base + 4 * i2)) & 0xFu) << 4);
            wd |= byte << (8 * i2);
        }
        reinterpret_cast<unsigned*>(&S.mbL[0][0])[idx] = wd;
    }
#pragma unroll
    for (int k = 0; k < 4; k++)
        (&S.Wa1[0][0][0])[tid + 256 * k] = Wa1[tid + 256 * k];
    (&S.Wv1[0][0][0])[tid] = Wv1[tid];
    (&S.Wa2[0][0])[tid]    = Wa2[tid];
    if (tid < 192) (&S.Wv2[0][0])[tid] = Wv2[tid];
    __syncthreads();

    float* a1 = out + OFF_A1 + (unsigned long long)bw * (H_ * N_ * N_);
    float* a2 = out + OFF_A2 + (unsigned long long)bw * (N_ * N_);

    const u64 qsc2 = pk2(QSCALE, QSCALE);

    // =========================== layer 1 (4 heads) ===========================
#pragma unroll 1
    for (int h = 0; h < H_; h++) {
        const int par = h & 1;
        float* QsH = &S.Qs[par][0][0];       // [N][20]
        const int vb = par * 4;              // VT row base for this head
        // stage 1 (packed): Q = QSCALE * X @ Wa1[h] ; VT rows vb..vb+3
        {
            u64 q2[8], v2[2];
#pragma unroll
            for (int j2 = 0; j2 < 8; j2++) q2[j2] = 0ull;
            v2[0] = 0ull; v2[1] = 0ull;
#pragma unroll
            for (int i = 0; i < P_; i++) {
                float xi = S.xT[i][tid];
                u64 xi2 = pk2(xi, xi);
                const ulonglong2* wa =
                    reinterpret_cast<const ulonglong2*>(&S.Wa1[h][i][0]);
#pragma unroll
                for (int j4 = 0; j4 < 4; j4++) {
                    ulonglong2 wp = wa[j4];
                    q2[j4*2+0] = fma2_(xi2, wp.x, q2[j4*2+0]);
                    q2[j4*2+1] = fma2_(xi2, wp.y, q2[j4*2+1]);
                }
                ulonglong2 wv =
                    *reinterpret_cast<const ulonglong2*>(&S.Wv1[h][i][0]);
                v2[0] = fma2_(xi2, wv.x, v2[0]);
                v2[1] = fma2_(xi2, wv.y, v2[1]);
            }
#pragma unroll
            for (int j2 = 0; j2 < 8; j2++) q2[j2] = mul2_(q2[j2], qsc2);
#pragma unroll
            for (int j4 = 0; j4 < 4; j4++) {
                float a0, b0, a1_, b1_;
                upk2(q2[j4*2+0], a0, b0);
                upk2(q2[j4*2+1], a1_, b1_);
                float4 t4 = make_float4(a0, b0, a1_, b1_);
                *reinterpret_cast<float4*>(&QsH[tid * 20 + j4 * 4]) = t4;
            }
            float va, vb_, vc, vd;
            upk2(v2[0], va, vb_); upk2(v2[1], vc, vd);
            S.VT[vb + 0][tid] = va; S.VT[vb + 1][tid] = vb_;
            S.VT[vb + 2][tid] = vc; S.VT[vb + 3][tid] = vd;
        }
        __syncthreads();

        float* a1h = a1 + h * N_ * N_;
#pragma unroll 1
        for (int rg = 0; rg < 8; rg++) {
            const int row0 = (wid << 5) + (rg << 2);
            // packed scores s2[c][r][pair]
            u64 s2[2][4][2];
#pragma unroll
            for (int c = 0; c < 2; c++)
#pragma unroll
                for (int r = 0; r < 4; r++) { s2[c][r][0] = 0ull; s2[c][r][1] = 0ull; }
#pragma unroll
            for (int kk = 0; kk < 4; kk++) {
                float4 q4[4];
#pragma unroll
                for (int r = 0; r < 4; r++)
                    q4[r] = *reinterpret_cast<const float4*>(
                        &QsH[(row0 + r) * 20 + kk * 4]);
#pragma unroll
                for (int k = 0; k < 4; k++) {
                    const int i = kk * 4 + k;
                    u64 qq[4];
#pragma unroll
                    for (int r = 0; r < 4; r++) {
                        float qk = (k == 0) ? q4[r].x : (k == 1) ? q4[r].y
                                 : (k == 2) ? q4[r].z : q4[r].w;
                        qq[r] = pk2(qk, qk);
                    }
#pragma unroll
                    for (int c = 0; c < 2; c++) {
                        ulonglong2 xv = *reinterpret_cast<const ulonglong2*>(
                            &S.xT[i][c * 128 + (lane << 2)]);
#pragma unroll
                        for (int r = 0; r < 4; r++) {
                            s2[c][r][0] = fma2_(qq[r], xv.x, s2[c][r][0]);
                            s2[c][r][1] = fma2_(qq[r], xv.y, s2[c][r][1]);
                        }
                    }
                }
            }
            // mask + ex2 in place; packed partial denominators
            float smr[4];
#pragma unroll
            for (int r = 0; r < 4; r++) {
                unsigned bb = S.mbL[row0 + r][lane];
                u64 dacc = 0ull;
#pragma unroll
                for (int c = 0; c < 2; c++)
#pragma unroll
                    for (int p = 0; p < 2; p++) {
                        float a_, b_; upk2(s2[c][r][p], a_, b_);
                        int kb = c * 4 + p * 2;
                        a_ = ((bb >> kb) & 1u)       ? ex2_(a_) : 0.f;
                        b_ = ((bb >> (kb + 1)) & 1u) ? ex2_(b_) : 0.f;
                        u64 e2 = pk2(a_, b_);
                        s2[c][r][p] = e2;
                        dacc = add2_(dacc, e2);
                    }
                float da, db; upk2(dacc, da, db);
                smr[r] = da + db;
            }
            // launch denominator chains (consumed AFTER aggregation)
            u64 d01 = warp_sum2(pk2(smr[0], smr[1]));
            u64 d23 = warp_sum2(pk2(smr[2], smr[3]));
            // aggregate RAW e (overlaps the SHFL chains)
            u64 acc2[4][HID_];
#pragma unroll
            for (int r = 0; r < 4; r++)
#pragma unroll
                for (int o = 0; o < HID_; o++) acc2[r][o] = 0ull;
#pragma unroll
            for (int c = 0; c < 2; c++) {
                const int m0 = c * 128 + (lane << 2);
#pragma unroll
                for (int o = 0; o < HID_; o++) {
                    ulonglong2 vv =
                        *reinterpret_cast<const ulonglong2*>(&S.VT[vb + o][m0]);
#pragma unroll
                    for (int r = 0; r < 4; r++) {
                        acc2[r][o] = fma2_(s2[c][r][0], vv.x, acc2[r][o]);
                        acc2[r][o] = fma2_(s2[c][r][1], vv.y, acc2[r][o]);
                    }
                }
            }
            // now consume denominators
            float inv[4];
            {
                float s0, s1, s2_, s3;
                upk2(d01, s0, s1); upk2(d23, s2_, s3);
                inv[0] = __frcp_rn(s0); inv[1] = __frcp_rn(s1);
                inv[2] = __frcp_rn(s2_); inv[3] = __frcp_rn(s3);
            }
            u64 inv2[4];
#pragma unroll
            for (int r = 0; r < 4; r++) inv2[r] = pk2(inv[r], inv[r]);
            // write normalized attn
            if (wA) {
#pragma unroll
                for (int c = 0; c < 2; c++) {
                    const int m0 = c * 128 + (lane << 2);
#pragma unroll
                    for (int r = 0; r < 4; r++) {
                        ulonglong2 st;
                        st.x = mul2_(s2[c][r][0], inv2[r]);
                        st.y = mul2_(s2[c][r][1], inv2[r]);
                        *reinterpret_cast<ulonglong2*>(&a1h[(row0 + r) * N_ + m0]) = st;
                    }
                }
            }
            // outputs: scale packed partial sums by inv, then reduce
#pragma unroll
            for (int r = 0; r < 4; r++) {
                float a0, b0, a1_, b1_, a2_, b2_, a3_, b3_;
                upk2(acc2[r][0], a0, b0);  upk2(acc2[r][1], a1_, b1_);
                upk2(acc2[r][2], a2_, b2_); upk2(acc2[r][3], a3_, b3_);
                u64 t01 = warp_sum2(mul2_(pk2(a0 + b0, a1_ + b1_), inv2[r]));
                u64 t23 = warp_sum2(mul2_(pk2(a2_ + b2_, a3_ + b3_), inv2[r]));
                if (lane == 0) {
                    float v0, v1, v2, v3;
                    upk2(t01, v0, v1); upk2(t23, v2, v3);
                    S.h1T[h * HID_ + 0][row0 + r] = v0;
                    S.h1T[h * HID_ + 1][row0 + r] = v1;
                    S.h1T[h * HID_ + 2][row0 + r] = v2;
                    S.h1T[h * HID_ + 3][row0 + r] = v3;
                }
            }
        }
        // no post-pass barrier: next head writes the other Qs buffer / VT rows
    }
    __syncthreads();   // all layer1 passes done (h1T complete) before layer2

    // ================================ layer 2 ================================
    {
        u64 q2[8], v2[6];
#pragma unroll
        for (int j2 = 0; j2 < 8; j2++) q2[j2] = 0ull;
#pragma unroll
        for (int o2 = 0; o2 < 6; o2++) v2[o2] = 0ull;
#pragma unroll
        for (int i = 0; i < P_; i++) {
            float xi = S.h1T[i][tid];
            u64 xi2 = pk2(xi, xi);
            const ulonglong2* wa =
                reinterpret_cast<const ulonglong2*>(&S.Wa2[i][0]);
#pragma unroll
            for (int j4 = 0; j4 < 4; j4++) {
                ulonglong2 wp = wa[j4];
                q2[j4*2+0] = fma2_(xi2, wp.x, q2[j4*2+0]);
                q2[j4*2+1] = fma2_(xi2, wp.y, q2[j4*2+1]);
            }
            const ulonglong2* wv =
                reinterpret_cast<const ulonglong2*>(&S.Wv2[i][0]);
#pragma unroll
            for (int o4 = 0; o4 < 3; o4++) {
                ulonglong2 wp = wv[o4];
                v2[o4*2+0] = fma2_(xi2, wp.x, v2[o4*2+0]);
                v2[o4*2+1] = fma2_(xi2, wp.y, v2[o4*2+1]);
            }
        }
#pragma unroll
        for (int j2 = 0; j2 < 8; j2++) q2[j2] = mul2_(q2[j2], qsc2);
        float* QsL2 = &S.Qs[0][0][0];
#pragma unroll
        for (int j4 = 0; j4 < 4; j4++) {
            float a0, b0, a1_, b1_;
            upk2(q2[j4*2+0], a0, b0);
            upk2(q2[j4*2+1], a1_, b1_);
            float4 t4 = make_float4(a0, b0, a1_, b1_);
            *reinterpret_cast<float4*>(&QsL2[tid * 20 + j4 * 4]) = t4;
        }
#pragma unroll
        for (int o2 = 0; o2 < 6; o2++) {
            float va, vb_; upk2(v2[o2], va, vb_);
            S.VT[2 * o2 + 0][tid] = va;
            S.VT[2 * o2 + 1][tid] = vb_;
        }
    }
    __syncthreads();

    const float* QsL2 = &S.Qs[0][0][0];
    // layer2: 4-row blocking, F-split aggregation (2 groups of 6 outputs)
#pragma unroll 1
    for (int rg = 0; rg < 8; rg++) {
        const int row0 = (wid << 5) + (rg << 2);
        u64 s2[2][4][2];
#pragma unroll
        for (int c = 0; c < 2; c++)
#pragma unroll
            for (int r = 0; r < 4; r++) { s2[c][r][0] = 0ull; s2[c][r][1] = 0ull; }
#pragma unroll
        for (int kk = 0; kk < 4; kk++) {
            float4 q4[4];
#pragma unroll
            for (int r = 0; r < 4; r++)
                q4[r] = *reinterpret_cast<const float4*>(
                    &QsL2[(row0 + r) * 20 + kk * 4]);
#pragma unroll
            for (int k = 0; k < 4; k++) {
                const int i = kk * 4 + k;
                u64 qq[4];
#pragma unroll
                for (int r = 0; r < 4; r++) {
                    float qk = (k == 0) ? q4[r].x : (k == 1) ? q4[r].y
                             : (k == 2) ? q4[r].z : q4[r].w;
                    qq[r] = pk2(qk, qk);
                }
#pragma unroll
                for (int c = 0; c < 2; c++) {
                    ulonglong2 xv = *reinterpret_cast<const ulonglong2*>(
                        &S.h1T[i][c * 128 + (lane << 2)]);
#pragma unroll
                    for (int r = 0; r < 4; r++) {
                        s2[c][r][0] = fma2_(qq[r], xv.x, s2[c][r][0]);
                        s2[c][r][1] = fma2_(qq[r], xv.y, s2[c][r][1]);
                    }
                }
            }
        }
        float smr[4];
#pragma unroll
        for (int r = 0; r < 4; r++) {
            unsigned bb = S.mbL[row0 + r][lane];
            u64 dacc = 0ull;
#pragma unroll
            for (int c = 0; c < 2; c++)
#pragma unroll
                for (int p = 0; p < 2; p++) {
                    float a_, b_; upk2(s2[c][r][p], a_, b_);
                    int kb = c * 4 + p * 2;
                    a_ = ((bb >> kb) & 1u)       ? ex2_(a_) : 0.f;
                    b_ = ((bb >> (kb + 1)) & 1u) ? ex2_(b_) : 0.f;
                    u64 e2 = pk2(a_, b_);
                    s2[c][r][p] = e2;
                    dacc = add2_(dacc, e2);
                }
            float da, db; upk2(dacc, da, db);
            smr[r] = da + db;
        }
        u64 d01 = warp_sum2(pk2(smr[0], smr[1]));
        u64 d23 = warp_sum2(pk2(smr[2], smr[3]));

        // ---- group 0: outputs 0..5, raw-e aggregation (overlaps chains) ----
        u64 acc2[4][6];
#pragma unroll
        for (int r = 0; r < 4; r++)
#pragma unroll
            for (int o = 0; o < 6; o++) acc2[r][o] = 0ull;
#pragma unroll
        for (int c = 0; c < 2; c++) {
            const int m0 = c * 128 + (lane << 2);
#pragma unroll
            for (int o = 0; o < 6; o++) {
                ulonglong2 vv = *reinterpret_cast<const ulonglong2*>(&S.VT[o][m0]);
#pragma unroll
                for (int r = 0; r < 4; r++) {
                    acc2[r][o] = fma2_(s2[c][r][0], vv.x, acc2[r][o]);
                    acc2[r][o] = fma2_(s2[c][r][1], vv.y, acc2[r][o]);
                }
            }
        }
        float inv[4];
        {
            float s0, s1, s2_, s3;
            upk2(d01, s0, s1); upk2(d23, s2_, s3);
            inv[0] = __frcp_rn(s0); inv[1] = __frcp_rn(s1);
            inv[2] = __frcp_rn(s2_); inv[3] = __frcp_rn(s3);
        }
        u64 inv2[4];
#pragma unroll
        for (int r = 0; r < 4; r++) inv2[r] = pk2(inv[r], inv[r]);
#pragma unroll
        for (int r = 0; r < 4; r++) {
#pragma unroll
            for (int p = 0; p < 3; p++) {
                float a0, b0, a1_, b1_;
                upk2(acc2[r][2 * p], a0, b0);
                upk2(acc2[r][2 * p + 1], a1_, b1_);
                u64 t = warp_sum2(mul2_(pk2(a0 + b0, a1_ + b1_), inv2[r]));
                if (lane == 0) {
                    float v0, v1; upk2(t, v0, v1);
                    out[((unsigned long long)bw * F_ + 2 * p) * N_ + row0 + r]     = v0;
                    out[((unsigned long long)bw * F_ + 2 * p + 1) * N_ + row0 + r] = v1;
                }
            }
        }
        // write normalized attn2
        if (wA) {
#pragma unroll
            for (int c = 0; c < 2; c++) {
                const int m0 = c * 128 + (lane << 2);
#pragma unroll
                for (int r = 0; r < 4; r++) {
                    ulonglong2 st;
                    st.x = mul2_(s2[c][r][0], inv2[r]);
                    st.y = mul2_(s2[c][r][1], inv2[r]);
                    *reinterpret_cast<ulonglong2*>(&a2[(row0 + r) * N_ + m0]) = st;
                }
            }
        }
        // ---- group 1: outputs 6..11 ----
#pragma unroll
        for (int r = 0; r < 4; r++)
#pragma unroll
            for (int o = 0; o < 6; o++) acc2[r][o] = 0ull;
#pragma unroll
        for (int c = 0; c < 2; c++) {
            const int m0 = c * 128 + (lane << 2);
#pragma unroll
            for (int o = 0; o < 6; o++) {
                ulonglong2 vv = *reinterpret_cast<const ulonglong2*>(&S.VT[6 + o][m0]);
#pragma unroll
                for (int r = 0; r < 4; r++) {
                    acc2[r][o] = fma2_(s2[c][r][0], vv.x, acc2[r][o]);
                    acc2[r][o] = fma2_(s2[c][r][1], vv.y, acc2[r][o]);
                }
            }
        }
#pragma unroll
        for (int r = 0; r < 4; r++) {
#pragma unroll
            for (int p = 0; p < 3; p++) {
                float a0, b0, a1_, b1_;
                upk2(acc2[r][2 * p], a0, b0);
                upk2(acc2[r][2 * p + 1], a1_, b1_);
                u64 t = warp_sum2(mul2_(pk2(a0 + b0, a1_ + b1_), inv2[r]));
                if (lane == 0) {
                    float v0, v1; upk2(t, v0, v1);
                    out[((unsigned long long)bw * F_ + 6 + 2 * p) * N_ + row0 + r]     = v0;
                    out[((unsigned long long)bw * F_ + 6 + 2 * p + 1) * N_ + row0 + r] = v1;
                }
            }
        }
    }
}

// ---------------------------------------------------------------------------
extern "C" void kernel_launch(void* const* d_in, const int* in_sizes, int n_in,
                              void* d_out, int out_size) {
    const float* inp  = (const float*)d_in[0];
    const int*   mask = (const int*)  d_in[1];
    const float* Wa1  = (const float*)d_in[2];
    const float* Wv1  = (const float*)d_in[3];
    const float* Wa2  = (const float*)d_in[4];
    const float* Wv2  = (const float*)d_in[5];
    float* out = (float*)d_out;

    const int wA = (out_size >= (int)(OFF_A2 + (unsigned long long)BW_ * N_ * N_)) ? 1 : 0;
    const int wW = (out_size >= (int)TOT_FULL) ? 1 : 0;

    cudaFuncSetAttribute(spatial_attn_kernel,
                         cudaFuncAttributeMaxDynamicSharedMemorySize,
                         (int)sizeof(Smem));

    pack_mask_kernel<<<N_, 256>>>(mask, Wv1, Wv2, out, wW);
    spatial_attn_kernel<<<BW_, 256, sizeof(Smem)>>>(inp, Wa1, Wv1, Wa2, Wv2, out, wA);
}

// round 14
// speedup vs baseline: 1.0025x; 1.0025x over previous
#include <cuda_runtime.h>

// ---------------------------------------------------------------------------
// SpatialAttn2: B=16, L=32, N=256, P=16, H=4, F=12, HID=4, W=16
// out[B,W,F,N] | attn1[B,W,H,N,N] | attn2[B,W,N,N] | Wv1 | Wv2
// R14: exact R11 skeleton + inter-CTA phase desync: odd-bw CTAs permute head
//      order (h^2) and rotate pass order (rg+4)&7 in both layers. Pure
//      permutation of independent work; output identical.
// ---------------------------------------------------------------------------

#define N_   256
#define P_   16
#define H_   4
#define F_   12
#define HID_ 4
#define W_   16
#define L_   32
#define BW_  256

static const unsigned long long OFF_A1  = 786432ull;
static const unsigned long long OFF_A2  = 786432ull + 67108864ull;
static const unsigned long long OFF_WV1 = 786432ull + 67108864ull + 16777216ull;
static const unsigned long long OFF_WV2 = OFF_WV1 + 256ull;
static const long long TOT_FULL = 84672960ll;

#define QSCALE 0.36067376022224085f   // 0.25 * log2(e)

__device__ unsigned int g_maskbits[N_ * 8];

typedef unsigned long long u64;

__device__ __forceinline__ u64 pk2(float a, float b) {
    u64 r; asm("mov.b64 %0, {%1,%2};" : "=l"(r) : "f"(a), "f"(b)); return r;
}
__device__ __forceinline__ void upk2(u64 v, float& a, float& b) {
    asm("mov.b64 {%0,%1}, %2;" : "=f"(a), "=f"(b) : "l"(v));
}
__device__ __forceinline__ u64 fma2_(u64 a, u64 b, u64 c) {
    u64 d; asm("fma.rn.f32x2 %0, %1, %2, %3;" : "=l"(d) : "l"(a), "l"(b), "l"(c)); return d;
}
__device__ __forceinline__ u64 mul2_(u64 a, u64 b) {
    u64 d; asm("mul.rn.f32x2 %0, %1, %2;" : "=l"(d) : "l"(a), "l"(b)); return d;
}
__device__ __forceinline__ u64 add2_(u64 a, u64 b) {
    u64 d; asm("add.rn.f32x2 %0, %1, %2;" : "=l"(d) : "l"(a), "l"(b)); return d;
}
__device__ __forceinline__ float ex2_(float x) {
    float y; asm("ex2.approx.f32 %0, %1;" : "=f"(y) : "f"(x)); return y;
}
__device__ __forceinline__ u64 warp_sum2(u64 v) {
#pragma unroll
    for (int o = 16; o > 0; o >>= 1)
        v = add2_(v, __shfl_xor_sync(0xffffffffu, v, o));
    return v;
}

// ---------------------------------------------------------------------------
__global__ void pack_mask_kernel(const int* __restrict__ mask,
                                 const float* __restrict__ Wv1,
                                 const float* __restrict__ Wv2,
                                 float* __restrict__ out, int wW) {
    const int tid = threadIdx.x;
    const int row = blockIdx.x;
    int v = mask[row * N_ + tid];
    unsigned int bal = __ballot_sync(0xffffffffu, v > 0);
    if ((tid & 31) == 0) g_maskbits[row * 8 + (tid >> 5)] = bal;
    if (wW && row == 0) {
        out[OFF_WV1 + tid] = Wv1[tid];
        if (tid < 192) out[OFF_WV2 + tid] = Wv2[tid];
    }
}

// ---------------------------------------------------------------------------
struct __align__(16) Smem {
    float xT [P_][N_];
    float h1T[P_][N_];
    float Qs [N_][20];
    float VT [F_][N_];
    unsigned char mbL[N_][32];   // per-(row,lane) mask byte
    float Wa1[H_][P_][P_];
    float Wv1[H_][P_][HID_];
    float Wa2[P_][P_];
    float Wv2[P_][F_];
};

__global__ void __launch_bounds__(256, 2)
spatial_attn_kernel(const float* __restrict__ inp,
                    const float* __restrict__ Wa1,
                    const float* __restrict__ Wv1,
                    const float* __restrict__ Wa2,
                    const float* __restrict__ Wv2,
                    float* __restrict__ out, int wA) {
    extern __shared__ char smraw[];
    Smem& S = *reinterpret_cast<Smem*>(smraw);
    const int tid  = threadIdx.x;
    const int lane = tid & 31;
    const int wid  = tid >> 5;
    const int bw   = blockIdx.x;
    const int b    = bw >> 4;
    const int w    = bw & 15;
    const int hx   = (bw & 1) << 1;   // head-order rotation for odd CTAs
    const int rgx  = (bw & 1) << 2;   // pass-order rotation for odd CTAs

    // ---- stage 0: load xT, weights; build mask byte table ------------------
#pragma unroll
    for (int p = 0; p < P_; p++)
        S.xT[p][tid] = inp[(b * L_ + w + p) * N_ + tid];
#pragma unroll
    for (int j = 0; j < 8; j++) {
        int idx = tid + 256 * j;
        int r = idx >> 3, g = idx & 7;
        unsigned A = g_maskbits[r * 8 + (g >> 1)];
        unsigned B = g_maskbits[r * 8 + 4 + (g >> 1)];
        int base = (g & 1) * 16;
        unsigned wd = 0;
#pragma unroll
        for (int i2 = 0; i2 < 4; i2++) {
            unsigned byte = ((A >> (base + 4 * i2)) & 0xFu)
                          | (((B >> (base + 4 * i2)) & 0xFu) << 4);
            wd |= byte << (8 * i2);
        }
        reinterpret_cast<unsigned*>(&S.mbL[0][0])[idx] = wd;
    }
#pragma unroll
    for (int k = 0; k < 4; k++)
        (&S.Wa1[0][0][0])[tid + 256 * k] = Wa1[tid + 256 * k];
    (&S.Wv1[0][0][0])[tid] = Wv1[tid];
    (&S.Wa2[0][0])[tid]    = Wa2[tid];
    if (tid < 192) (&S.Wv2[0][0])[tid] = Wv2[tid];
    __syncthreads();

    float* a1 = out + OFF_A1 + (unsigned long long)bw * (H_ * N_ * N_);
    float* a2 = out + OFF_A2 + (unsigned long long)bw * (N_ * N_);

    // =========================== layer 1 (4 heads) ===========================
#pragma unroll 1
    for (int h0 = 0; h0 < H_; h0++) {
        const int h = h0 ^ hx;           // CTA-parity head rotation
        // stage 1: Q = QSCALE * X @ Wa1[h] ; VT = (X @ Wv1[h])^T
        {
            float q[P_], v[HID_];
#pragma unroll
            for (int j = 0; j < P_; j++) q[j] = 0.f;
#pragma unroll
            for (int o = 0; o < HID_; o++) v[o] = 0.f;
#pragma unroll
            for (int i = 0; i < P_; i++) {
                float xi = S.xT[i][tid];
#pragma unroll
                for (int j = 0; j < P_; j++) q[j] += xi * S.Wa1[h][i][j];
#pragma unroll
                for (int o = 0; o < HID_; o++) v[o] += xi * S.Wv1[h][i][o];
            }
#pragma unroll
            for (int j4 = 0; j4 < 4; j4++) {
                float4 t4 = make_float4(q[j4*4+0]*QSCALE, q[j4*4+1]*QSCALE,
                                        q[j4*4+2]*QSCALE, q[j4*4+3]*QSCALE);
                *reinterpret_cast<float4*>(&S.Qs[tid][j4*4]) = t4;
            }
#pragma unroll
            for (int o = 0; o < HID_; o++) S.VT[o][tid] = v[o];
        }
        __syncthreads();

        float* a1h = a1 + h * N_ * N_;
#pragma unroll 1
        for (int rg0 = 0; rg0 < 8; rg0++) {
            const int rg   = (rg0 + rgx) & 7;   // CTA-parity pass rotation
            const int row0 = (wid << 5) + (rg << 2);
            // packed scores s2[c][r][pair]
            u64 s2[2][4][2];
#pragma unroll
            for (int c = 0; c < 2; c++)
#pragma unroll
                for (int r = 0; r < 4; r++) { s2[c][r][0] = 0ull; s2[c][r][1] = 0ull; }
#pragma unroll
            for (int kk = 0; kk < 4; kk++) {
                float4 q4[4];
#pragma unroll
                for (int r = 0; r < 4; r++)
                    q4[r] = *reinterpret_cast<const float4*>(&S.Qs[row0 + r][kk * 4]);
#pragma unroll
                for (int k = 0; k < 4; k++) {
                    const int i = kk * 4 + k;
                    u64 qq[4];
#pragma unroll
                    for (int r = 0; r < 4; r++) {
                        float qk = (k == 0) ? q4[r].x : (k == 1) ? q4[r].y
                                 : (k == 2) ? q4[r].z : q4[r].w;
                        qq[r] = pk2(qk, qk);
                    }
#pragma unroll
                    for (int c = 0; c < 2; c++) {
                        ulonglong2 xv = *reinterpret_cast<const ulonglong2*>(
                            &S.xT[i][c * 128 + (lane << 2)]);
#pragma unroll
                        for (int r = 0; r < 4; r++) {
                            s2[c][r][0] = fma2_(qq[r], xv.x, s2[c][r][0]);
                            s2[c][r][1] = fma2_(qq[r], xv.y, s2[c][r][1]);
                        }
                    }
                }
            }
            // mask + ex2 in place; packed partial denominators
            float smr[4];
#pragma unroll
            for (int r = 0; r < 4; r++) {
                unsigned bb = S.mbL[row0 + r][lane];
                u64 dacc = 0ull;
#pragma unroll
                for (int c = 0; c < 2; c++)
#pragma unroll
                    for (int p = 0; p < 2; p++) {
                        float a_, b_; upk2(s2[c][r][p], a_, b_);
                        int kb = c * 4 + p * 2;
                        a_ = ((bb >> kb) & 1u)       ? ex2_(a_) : 0.f;
                        b_ = ((bb >> (kb + 1)) & 1u) ? ex2_(b_) : 0.f;
                        u64 e2 = pk2(a_, b_);
                        s2[c][r][p] = e2;
                        dacc = add2_(dacc, e2);
                    }
                float da, db; upk2(dacc, da, db);
                smr[r] = da + db;
            }
            // launch denominator chains (consumed AFTER aggregation)
            u64 d01 = warp_sum2(pk2(smr[0], smr[1]));
            u64 d23 = warp_sum2(pk2(smr[2], smr[3]));
            // aggregate RAW e (overlaps the SHFL chains)
            u64 acc2[4][HID_];
#pragma unroll
            for (int r = 0; r < 4; r++)
#pragma unroll
                for (int o = 0; o < HID_; o++) acc2[r][o] = 0ull;
#pragma unroll
            for (int c = 0; c < 2; c++) {
                const int m0 = c * 128 + (lane << 2);
#pragma unroll
                for (int o = 0; o < HID_; o++) {
                    ulonglong2 vv = *reinterpret_cast<const ulonglong2*>(&S.VT[o][m0]);
#pragma unroll
                    for (int r = 0; r < 4; r++) {
                        acc2[r][o] = fma2_(s2[c][r][0], vv.x, acc2[r][o]);
                        acc2[r][o] = fma2_(s2[c][r][1], vv.y, acc2[r][o]);
                    }
                }
            }
            // now consume denominators
            float inv[4];
            {
                float s0, s1, s2_, s3;
                upk2(d01, s0, s1); upk2(d23, s2_, s3);
                inv[0] = __frcp_rn(s0); inv[1] = __frcp_rn(s1);
                inv[2] = __frcp_rn(s2_); inv[3] = __frcp_rn(s3);
            }
            u64 inv2[4];
#pragma unroll
            for (int r = 0; r < 4; r++) inv2[r] = pk2(inv[r], inv[r]);
            // write normalized attn
            if (wA) {
#pragma unroll
                for (int c = 0; c < 2; c++) {
                    const int m0 = c * 128 + (lane << 2);
#pragma unroll
                    for (int r = 0; r < 4; r++) {
                        ulonglong2 st;
                        st.x = mul2_(s2[c][r][0], inv2[r]);
                        st.y = mul2_(s2[c][r][1], inv2[r]);
                        *reinterpret_cast<ulonglong2*>(&a1h[(row0 + r) * N_ + m0]) = st;
                    }
                }
            }
            // outputs: scale packed partial sums by inv, then reduce
#pragma unroll
            for (int r = 0; r < 4; r++) {
                float a0, b0, a1_, b1_, a2_, b2_, a3_, b3_;
                upk2(acc2[r][0], a0, b0);  upk2(acc2[r][1], a1_, b1_);
                upk2(acc2[r][2], a2_, b2_); upk2(acc2[r][3], a3_, b3_);
                u64 t01 = warp_sum2(mul2_(pk2(a0 + b0, a1_ + b1_), inv2[r]));
                u64 t23 = warp_sum2(mul2_(pk2(a2_ + b2_, a3_ + b3_), inv2[r]));
                if (lane == 0) {
                    float v0, v1, v2, v3;
                    upk2(t01, v0, v1); upk2(t23, v2, v3);
                    S.h1T[h * HID_ + 0][row0 + r] = v0;
                    S.h1T[h * HID_ + 1][row0 + r] = v1;
                    S.h1T[h * HID_ + 2][row0 + r] = v2;
                    S.h1T[h * HID_ + 3][row0 + r] = v3;
                }
            }
        }
        __syncthreads();
    }

    // ================================ layer 2 ================================
    {
        float q[P_], v[F_];
#pragma unroll
        for (int j = 0; j < P_; j++) q[j] = 0.f;
#pragma unroll
        for (int o = 0; o < F_; o++) v[o] = 0.f;
#pragma unroll
        for (int i = 0; i < P_; i++) {
            float xi = S.h1T[i][tid];
#pragma unroll
            for (int j = 0; j < P_; j++) q[j] += xi * S.Wa2[i][j];
#pragma unroll
            for (int o = 0; o < F_; o++) v[o] += xi * S.Wv2[i][o];
        }
#pragma unroll
        for (int j4 = 0; j4 < 4; j4++) {
            float4 t4 = make_float4(q[j4*4+0]*QSCALE, q[j4*4+1]*QSCALE,
                                    q[j4*4+2]*QSCALE, q[j4*4+3]*QSCALE);
            *reinterpret_cast<float4*>(&S.Qs[tid][j4*4]) = t4;
        }
#pragma unroll
        for (int o = 0; o < F_; o++) S.VT[o][tid] = v[o];
    }
    __syncthreads();

    // layer2: 4-row blocking, F-split aggregation (2 groups of 6 outputs)
#pragma unroll 1
    for (int rg0 = 0; rg0 < 8; rg0++) {
        const int rg   = (rg0 + rgx) & 7;
        const int row0 = (wid << 5) + (rg << 2);
        u64 s2[2][4][2];
#pragma unroll
        for (int c = 0; c < 2; c++)
#pragma unroll
            for (int r = 0; r < 4; r++) { s2[c][r][0] = 0ull; s2[c][r][1] = 0ull; }
#pragma unroll
        for (int kk = 0; kk < 4; kk++) {
            float4 q4[4];
#pragma unroll
            for (int r = 0; r < 4; r++)
                q4[r] = *reinterpret_cast<const float4*>(&S.Qs[row0 + r][kk * 4]);
#pragma unroll
            for (int k = 0; k < 4; k++) {
                const int i = kk * 4 + k;
                u64 qq[4];
#pragma unroll
                for (int r = 0; r < 4; r++) {
                    float qk = (k == 0) ? q4[r].x : (k == 1) ? q4[r].y
                             : (k == 2) ? q4[r].z : q4[r].w;
                    qq[r] = pk2(qk, qk);
                }
#pragma unroll
                for (int c = 0; c < 2; c++) {
                    ulonglong2 xv = *reinterpret_cast<const ulonglong2*>(
                        &S.h1T[i][c * 128 + (lane << 2)]);
#pragma unroll
                    for (int r = 0; r < 4; r++) {
                        s2[c][r][0] = fma2_(qq[r], xv.x, s2[c][r][0]);
                        s2[c][r][1] = fma2_(qq[r], xv.y, s2[c][r][1]);
                    }
                }
            }
        }
        float smr[4];
#pragma unroll
        for (int r = 0; r < 4; r++) {
            unsigned bb = S.mbL[row0 + r][lane];
            u64 dacc = 0ull;
#pragma unroll
            for (int c = 0; c < 2; c++)
#pragma unroll
                for (int p = 0; p < 2; p++) {
                    float a_, b_; upk2(s2[c][r][p], a_, b_);
                    int kb = c * 4 + p * 2;
                    a_ = ((bb >> kb) & 1u)       ? ex2_(a_) : 0.f;
                    b_ = ((bb >> (kb + 1)) & 1u) ? ex2_(b_) : 0.f;
                    u64 e2 = pk2(a_, b_);
                    s2[c][r][p] = e2;
                    dacc = add2_(dacc, e2);
                }
            float da, db; upk2(dacc, da, db);
            smr[r] = da + db;
        }
        u64 d01 = warp_sum2(pk2(smr[0], smr[1]));
        u64 d23 = warp_sum2(pk2(smr[2], smr[3]));

        // ---- group 0: outputs 0..5, raw-e aggregation (overlaps chains) ----
        u64 acc2[4][6];
#pragma unroll
        for (int r = 0; r < 4; r++)
#pragma unroll
            for (int o = 0; o < 6; o++) acc2[r][o] = 0ull;
#pragma unroll
        for (int c = 0; c < 2; c++) {
            const int m0 = c * 128 + (lane << 2);
#pragma unroll
            for (int o = 0; o < 6; o++) {
                ulonglong2 vv = *reinterpret_cast<const ulonglong2*>(&S.VT[o][m0]);
#pragma unroll
                for (int r = 0; r < 4; r++) {
                    acc2[r][o] = fma2_(s2[c][r][0], vv.x, acc2[r][o]);
                    acc2[r][o] = fma2_(s2[c][r][1], vv.y, acc2[r][o]);
                }
            }
        }
        float inv[4];
        {
            float s0, s1, s2_, s3;
            upk2(d01, s0, s1); upk2(d23, s2_, s3);
            inv[0] = __frcp_rn(s0); inv[1] = __frcp_rn(s1);
            inv[2] = __frcp_rn(s2_); inv[3] = __frcp_rn(s3);
        }
        u64 inv2[4];
#pragma unroll
        for (int r = 0; r < 4; r++) inv2[r] = pk2(inv[r], inv[r]);
#pragma unroll
        for (int r = 0; r < 4; r++) {
#pragma unroll
            for (int p = 0; p < 3; p++) {
                float a0, b0, a1_, b1_;
                upk2(acc2[r][2 * p], a0, b0);
                upk2(acc2[r][2 * p + 1], a1_, b1_);
                u64 t = warp_sum2(mul2_(pk2(a0 + b0, a1_ + b1_), inv2[r]));
                if (lane == 0) {
                    float v0, v1; upk2(t, v0, v1);
                    out[((unsigned long long)bw * F_ + 2 * p) * N_ + row0 + r]     = v0;
                    out[((unsigned long long)bw * F_ + 2 * p + 1) * N_ + row0 + r] = v1;
                }
            }
        }
        // write normalized attn2
        if (wA) {
#pragma unroll
            for (int c = 0; c < 2; c++) {
                const int m0 = c * 128 + (lane << 2);
#pragma unroll
                for (int r = 0; r < 4; r++) {
                    ulonglong2 st;
                    st.x = mul2_(s2[c][r][0], inv2[r]);
                    st.y = mul2_(s2[c][r][1], inv2[r]);
                    *reinterpret_cast<ulonglong2*>(&a2[(row0 + r) * N_ + m0]) = st;
                }
            }
        }
        // ---- group 1: outputs 6..11 ----
#pragma unroll
        for (int r = 0; r < 4; r++)
#pragma unroll
            for (int o = 0; o < 6; o++) acc2[r][o] = 0ull;
#pragma unroll
        for (int c = 0; c < 2; c++) {
            const int m0 = c * 128 + (lane << 2);
#pragma unroll
            for (int o = 0; o < 6; o++) {
                ulonglong2 vv = *reinterpret_cast<const ulonglong2*>(&S.VT[6 + o][m0]);
#pragma unroll
                for (int r = 0; r < 4; r++) {
                    acc2[r][o] = fma2_(s2[c][r][0], vv.x, acc2[r][o]);
                    acc2[r][o] = fma2_(s2[c][r][1], vv.y, acc2[r][o]);
                }
            }
        }
#pragma unroll
        for (int r = 0; r < 4; r++) {
#pragma unroll
            for (int p = 0; p < 3; p++) {
                float a0, b0, a1_, b1_;
                upk2(acc2[r][2 * p], a0, b0);
                upk2(acc2[r][2 * p + 1], a1_, b1_);
                u64 t = warp_sum2(mul2_(pk2(a0 + b0, a1_ + b1_), inv2[r]));
                if (lane == 0) {
                    float v0, v1; upk2(t, v0, v1);
                    out[((unsigned long long)bw * F_ + 6 + 2 * p) * N_ + row0 + r]     = v0;
                    out[((unsigned long long)bw * F_ + 6 + 2 * p + 1) * N_ + row0 + r] = v1;
                }
            }
        }
    }
}

// ---------------------------------------------------------------------------
extern "C" void kernel_launch(void* const* d_in, const int* in_sizes, int n_in,
                              void* d_out, int out_size) {
    const float* inp  = (const float*)d_in[0];
    const int*   mask = (const int*)  d_in[1];
    const float* Wa1  = (const float*)d_in[2];
    const float* Wv1  = (const float*)d_in[3];
    const float* Wa2  = (const float*)d_in[4];
    const float* Wv2  = (const float*)d_in[5];
    float* out = (float*)d_out;

    const int wA = (out_size >= (int)(OFF_A2 + (unsigned long long)BW_ * N_ * N_)) ? 1 : 0;
    const int wW = (out_size >= (int)TOT_FULL) ? 1 : 0;

    cudaFuncSetAttribute(spatial_attn_kernel,
                         cudaFuncAttributeMaxDynamicSharedMemorySize,
                         (int)sizeof(Smem));

    pack_mask_kernel<<<N_, 256>>>(mask, Wv1, Wv2, out, wW);
    spatial_attn_kernel<<<BW_, 256, sizeof(Smem)>>>(inp, Wa1, Wv1, Wa2, Wv2, out, wA);
}

// round 15
// speedup vs baseline: 1.0060x; 1.0035x over previous
#include <cuda_runtime.h>

// ---------------------------------------------------------------------------
// SpatialAttn2: B=16, L=32, N=256, P=16, H=4, F=12, HID=4, W=16
// out[B,W,F,N] | attn1[B,W,H,N,N] | attn2[B,W,N,N] | Wv1 | Wv2
// R15: R11 (best) + st.global.cs streaming attn stores + unpadded Qs[N][16]
//      (broadcast reads are conflict-free; padding was dead weight).
// ---------------------------------------------------------------------------

#define N_   256
#define P_   16
#define H_   4
#define F_   12
#define HID_ 4
#define W_   16
#define L_   32
#define BW_  256

static const unsigned long long OFF_A1  = 786432ull;
static const unsigned long long OFF_A2  = 786432ull + 67108864ull;
static const unsigned long long OFF_WV1 = 786432ull + 67108864ull + 16777216ull;
static const unsigned long long OFF_WV2 = OFF_WV1 + 256ull;
static const long long TOT_FULL = 84672960ll;

#define QSCALE 0.36067376022224085f   // 0.25 * log2(e)

__device__ unsigned int g_maskbits[N_ * 8];

typedef unsigned long long u64;

__device__ __forceinline__ u64 pk2(float a, float b) {
    u64 r; asm("mov.b64 %0, {%1,%2};" : "=l"(r) : "f"(a), "f"(b)); return r;
}
__device__ __forceinline__ void upk2(u64 v, float& a, float& b) {
    asm("mov.b64 {%0,%1}, %2;" : "=f"(a), "=f"(b) : "l"(v));
}
__device__ __forceinline__ u64 fma2_(u64 a, u64 b, u64 c) {
    u64 d; asm("fma.rn.f32x2 %0, %1, %2, %3;" : "=l"(d) : "l"(a), "l"(b), "l"(c)); return d;
}
__device__ __forceinline__ u64 mul2_(u64 a, u64 b) {
    u64 d; asm("mul.rn.f32x2 %0, %1, %2;" : "=l"(d) : "l"(a), "l"(b)); return d;
}
__device__ __forceinline__ u64 add2_(u64 a, u64 b) {
    u64 d; asm("add.rn.f32x2 %0, %1, %2;" : "=l"(d) : "l"(a), "l"(b)); return d;
}
__device__ __forceinline__ float ex2_(float x) {
    float y; asm("ex2.approx.f32 %0, %1;" : "=f"(y) : "f"(x)); return y;
}
__device__ __forceinline__ void stcs2(void* p, u64 x, u64 y) {
    asm volatile("st.global.cs.v2.u64 [%0], {%1, %2};"
                 :: "l"(p), "l"(x), "l"(y) : "memory");
}
__device__ __forceinline__ u64 warp_sum2(u64 v) {
#pragma unroll
    for (int o = 16; o > 0; o >>= 1)
        v = add2_(v, __shfl_xor_sync(0xffffffffu, v, o));
    return v;
}

// ---------------------------------------------------------------------------
__global__ void pack_mask_kernel(const int* __restrict__ mask,
                                 const float* __restrict__ Wv1,
                                 const float* __restrict__ Wv2,
                                 float* __restrict__ out, int wW) {
    const int tid = threadIdx.x;
    const int row = blockIdx.x;
    int v = mask[row * N_ + tid];
    unsigned int bal = __ballot_sync(0xffffffffu, v > 0);
    if ((tid & 31) == 0) g_maskbits[row * 8 + (tid >> 5)] = bal;
    if (wW && row == 0) {
        out[OFF_WV1 + tid] = Wv1[tid];
        if (tid < 192) out[OFF_WV2 + tid] = Wv2[tid];
    }
}

// ---------------------------------------------------------------------------
struct __align__(16) Smem {
    float xT [P_][N_];
    float h1T[P_][N_];
    float Qs [N_][P_];           // unpadded: reads are warp-uniform broadcasts
    float VT [F_][N_];
    unsigned char mbL[N_][32];   // per-(row,lane) mask byte
    float Wa1[H_][P_][P_];
    float Wv1[H_][P_][HID_];
    float Wa2[P_][P_];
    float Wv2[P_][F_];
};

__global__ void __launch_bounds__(256, 2)
spatial_attn_kernel(const float* __restrict__ inp,
                    const float* __restrict__ Wa1,
                    const float* __restrict__ Wv1,
                    const float* __restrict__ Wa2,
                    const float* __restrict__ Wv2,
                    float* __restrict__ out, int wA) {
    extern __shared__ char smraw[];
    Smem& S = *reinterpret_cast<Smem*>(smraw);
    const int tid  = threadIdx.x;
    const int lane = tid & 31;
    const int wid  = tid >> 5;
    const int bw   = blockIdx.x;
    const int b    = bw >> 4;
    const int w    = bw & 15;

    // ---- stage 0: load xT, weights; build mask byte table ------------------
#pragma unroll
    for (int p = 0; p < P_; p++)
        S.xT[p][tid] = inp[(b * L_ + w + p) * N_ + tid];
#pragma unroll
    for (int j = 0; j < 8; j++) {
        int idx = tid + 256 * j;
        int r = idx >> 3, g = idx & 7;
        unsigned A = g_maskbits[r * 8 + (g >> 1)];
        unsigned B = g_maskbits[r * 8 + 4 + (g >> 1)];
        int base = (g & 1) * 16;
        unsigned wd = 0;
#pragma unroll
        for (int i2 = 0; i2 < 4; i2++) {
            unsigned byte = ((A >> (base + 4 * i2)) & 0xFu)
                          | (((B >> (base + 4 * i2)) & 0xFu) << 4);
            wd |= byte << (8 * i2);
        }
        reinterpret_cast<unsigned*>(&S.mbL[0][0])[idx] = wd;
    }
#pragma unroll
    for (int k = 0; k < 4; k++)
        (&S.Wa1[0][0][0])[tid + 256 * k] = Wa1[tid + 256 * k];
    (&S.Wv1[0][0][0])[tid] = Wv1[tid];
    (&S.Wa2[0][0])[tid]    = Wa2[tid];
    if (tid < 192) (&S.Wv2[0][0])[tid] = Wv2[tid];
    __syncthreads();

    float* a1 = out + OFF_A1 + (unsigned long long)bw * (H_ * N_ * N_);
    float* a2 = out + OFF_A2 + (unsigned long long)bw * (N_ * N_);

    // =========================== layer 1 (4 heads) ===========================
#pragma unroll 1
    for (int h = 0; h < H_; h++) {
        // stage 1: Q = QSCALE * X @ Wa1[h] ; VT = (X @ Wv1[h])^T
        {
            float q[P_], v[HID_];
#pragma unroll
            for (int j = 0; j < P_; j++) q[j] = 0.f;
#pragma unroll
            for (int o = 0; o < HID_; o++) v[o] = 0.f;
#pragma unroll
            for (int i = 0; i < P_; i++) {
                float xi = S.xT[i][tid];
#pragma unroll
                for (int j = 0; j < P_; j++) q[j] += xi * S.Wa1[h][i][j];
#pragma unroll
                for (int o = 0; o < HID_; o++) v[o] += xi * S.Wv1[h][i][o];
            }
#pragma unroll
            for (int j4 = 0; j4 < 4; j4++) {
                float4 t4 = make_float4(q[j4*4+0]*QSCALE, q[j4*4+1]*QSCALE,
                                        q[j4*4+2]*QSCALE, q[j4*4+3]*QSCALE);
                *reinterpret_cast<float4*>(&S.Qs[tid][j4*4]) = t4;
            }
#pragma unroll
            for (int o = 0; o < HID_; o++) S.VT[o][tid] = v[o];
        }
        __syncthreads();

        float* a1h = a1 + h * N_ * N_;
#pragma unroll 1
        for (int rg = 0; rg < 8; rg++) {
            const int row0 = (wid << 5) + (rg << 2);
            // packed scores s2[c][r][pair]
            u64 s2[2][4][2];
#pragma unroll
            for (int c = 0; c < 2; c++)
#pragma unroll
                for (int r = 0; r < 4; r++) { s2[c][r][0] = 0ull; s2[c][r][1] = 0ull; }
#pragma unroll
            for (int kk = 0; kk < 4; kk++) {
                float4 q4[4];
#pragma unroll
                for (int r = 0; r < 4; r++)
                    q4[r] = *reinterpret_cast<const float4*>(&S.Qs[row0 + r][kk * 4]);
#pragma unroll
                for (int k = 0; k < 4; k++) {
                    const int i = kk * 4 + k;
                    u64 qq[4];
#pragma unroll
                    for (int r = 0; r < 4; r++) {
                        float qk = (k == 0) ? q4[r].x : (k == 1) ? q4[r].y
                                 : (k == 2) ? q4[r].z : q4[r].w;
                        qq[r] = pk2(qk, qk);
                    }
#pragma unroll
                    for (int c = 0; c < 2; c++) {
                        ulonglong2 xv = *reinterpret_cast<const ulonglong2*>(
                            &S.xT[i][c * 128 + (lane << 2)]);
#pragma unroll
                        for (int r = 0; r < 4; r++) {
                            s2[c][r][0] = fma2_(qq[r], xv.x, s2[c][r][0]);
                            s2[c][r][1] = fma2_(qq[r], xv.y, s2[c][r][1]);
                        }
                    }
                }
            }
            // mask + ex2 in place; packed partial denominators
            float smr[4];
#pragma unroll
            for (int r = 0; r < 4; r++) {
                unsigned bb = S.mbL[row0 + r][lane];
                u64 dacc = 0ull;
#pragma unroll
                for (int c = 0; c < 2; c++)
#pragma unroll
                    for (int p = 0; p < 2; p++) {
                        float a_, b_; upk2(s2[c][r][p], a_, b_);
                        int kb = c * 4 + p * 2;
                        a_ = ((bb >> kb) & 1u)       ? ex2_(a_) : 0.f;
                        b_ = ((bb >> (kb + 1)) & 1u) ? ex2_(b_) : 0.f;
                        u64 e2 = pk2(a_, b_);
                        s2[c][r][p] = e2;
                        dacc = add2_(dacc, e2);
                    }
                float da, db; upk2(dacc, da, db);
                smr[r] = da + db;
            }
            // launch denominator chains (consumed AFTER aggregation)
            u64 d01 = warp_sum2(pk2(smr[0], smr[1]));
            u64 d23 = warp_sum2(pk2(smr[2], smr[3]));
            // aggregate RAW e (overlaps the SHFL chains)
            u64 acc2[4][HID_];
#pragma unroll
            for (int r = 0; r < 4; r++)
#pragma unroll
                for (int o = 0; o < HID_; o++) acc2[r][o] = 0ull;
#pragma unroll
            for (int c = 0; c < 2; c++) {
                const int m0 = c * 128 + (lane << 2);
#pragma unroll
                for (int o = 0; o < HID_; o++) {
                    ulonglong2 vv = *reinterpret_cast<const ulonglong2*>(&S.VT[o][m0]);
#pragma unroll
                    for (int r = 0; r < 4; r++) {
                        acc2[r][o] = fma2_(s2[c][r][0], vv.x, acc2[r][o]);
                        acc2[r][o] = fma2_(s2[c][r][1], vv.y, acc2[r][o]);
                    }
                }
            }
            // now consume denominators
            float inv[4];
            {
                float s0, s1, s2_, s3;
                upk2(d01, s0, s1); upk2(d23, s2_, s3);
                inv[0] = __frcp_rn(s0); inv[1] = __frcp_rn(s1);
                inv[2] = __frcp_rn(s2_); inv[3] = __frcp_rn(s3);
            }
            u64 inv2[4];
#pragma unroll
            for (int r = 0; r < 4; r++) inv2[r] = pk2(inv[r], inv[r]);
            // write normalized attn (streaming)
            if (wA) {
#pragma unroll
                for (int c = 0; c < 2; c++) {
                    const int m0 = c * 128 + (lane << 2);
#pragma unroll
                    for (int r = 0; r < 4; r++) {
                        stcs2(&a1h[(row0 + r) * N_ + m0],
                              mul2_(s2[c][r][0], inv2[r]),
                              mul2_(s2[c][r][1], inv2[r]));
                    }
                }
            }
            // outputs: scale packed partial sums by inv, then reduce
#pragma unroll
            for (int r = 0; r < 4; r++) {
                float a0, b0, a1_, b1_, a2_, b2_, a3_, b3_;
                upk2(acc2[r][0], a0, b0);  upk2(acc2[r][1], a1_, b1_);
                upk2(acc2[r][2], a2_, b2_); upk2(acc2[r][3], a3_, b3_);
                u64 t01 = warp_sum2(mul2_(pk2(a0 + b0, a1_ + b1_), inv2[r]));
                u64 t23 = warp_sum2(mul2_(pk2(a2_ + b2_, a3_ + b3_), inv2[r]));
                if (lane == 0) {
                    float v0, v1, v2, v3;
                    upk2(t01, v0, v1); upk2(t23, v2, v3);
                    S.h1T[h * HID_ + 0][row0 + r] = v0;
                    S.h1T[h * HID_ + 1][row0 + r] = v1;
                    S.h1T[h * HID_ + 2][row0 + r] = v2;
                    S.h1T[h * HID_ + 3][row0 + r] = v3;
                }
            }
        }
        __syncthreads();
    }

    // ================================ layer 2 ================================
    {
        float q[P_], v[F_];
#pragma unroll
        for (int j = 0; j < P_; j++) q[j] = 0.f;
#pragma unroll
        for (int o = 0; o < F_; o++) v[o] = 0.f;
#pragma unroll
        for (int i = 0; i < P_; i++) {
            float xi = S.h1T[i][tid];
#pragma unroll
            for (int j = 0; j < P_; j++) q[j] += xi * S.Wa2[i][j];
#pragma unroll
            for (int o = 0; o < F_; o++) v[o] += xi * S.Wv2[i][o];
        }
#pragma unroll
        for (int j4 = 0; j4 < 4; j4++) {
            float4 t4 = make_float4(q[j4*4+0]*QSCALE, q[j4*4+1]*QSCALE,
                                    q[j4*4+2]*QSCALE, q[j4*4+3]*QSCALE);
            *reinterpret_cast<float4*>(&S.Qs[tid][j4*4]) = t4;
        }
#pragma unroll
        for (int o = 0; o < F_; o++) S.VT[o][tid] = v[o];
    }
    __syncthreads();

    // layer2: 4-row blocking, F-split aggregation (2 groups of 6 outputs)
#pragma unroll 1
    for (int rg = 0; rg < 8; rg++) {
        const int row0 = (wid << 5) + (rg << 2);
        u64 s2[2][4][2];
#pragma unroll
        for (int c = 0; c < 2; c++)
#pragma unroll
            for (int r = 0; r < 4; r++) { s2[c][r][0] = 0ull; s2[c][r][1] = 0ull; }
#pragma unroll
        for (int kk = 0; kk < 4; kk++) {
            float4 q4[4];
#pragma unroll
            for (int r = 0; r < 4; r++)
                q4[r] = *reinterpret_cast<const float4*>(&S.Qs[row0 + r][kk * 4]);
#pragma unroll
            for (int k = 0; k < 4; k++) {
                const int i = kk * 4 + k;
                u64 qq[4];
#pragma unroll
                for (int r = 0; r < 4; r++) {
                    float qk = (k == 0) ? q4[r].x : (k == 1) ? q4[r].y
                             : (k == 2) ? q4[r].z : q4[r].w;
                    qq[r] = pk2(qk, qk);
                }
#pragma unroll
                for (int c = 0; c < 2; c++) {
                    ulonglong2 xv = *reinterpret_cast<const ulonglong2*>(
                        &S.h1T[i][c * 128 + (lane << 2)]);
#pragma unroll
                    for (int r = 0; r < 4; r++) {
                        s2[c][r][0] = fma2_(qq[r], xv.x, s2[c][r][0]);
                        s2[c][r][1] = fma2_(qq[r], xv.y, s2[c][r][1]);
                    }
                }
            }
        }
        float smr[4];
#pragma unroll
        for (int r = 0; r < 4; r++) {
            unsigned bb = S.mbL[row0 + r][lane];
            u64 dacc = 0ull;
#pragma unroll
            for (int c = 0; c < 2; c++)
#pragma unroll
                for (int p = 0; p < 2; p++) {
                    float a_, b_; upk2(s2[c][r][p], a_, b_);
                    int kb = c * 4 + p * 2;
                    a_ = ((bb >> kb) & 1u)       ? ex2_(a_) : 0.f;
                    b_ = ((bb >> (kb + 1)) & 1u) ? ex2_(b_) : 0.f;
                    u64 e2 = pk2(a_, b_);
                    s2[c][r][p] = e2;
                    dacc = add2_(dacc, e2);
                }
            float da, db; upk2(dacc, da, db);
            smr[r] = da + db;
        }
        u64 d01 = warp_sum2(pk2(smr[0], smr[1]));
        u64 d23 = warp_sum2(pk2(smr[2], smr[3]));

        // ---- group 0: outputs 0..5, raw-e aggregation (overlaps chains) ----
        u64 acc2[4][6];
#pragma unroll
        for (int r = 0; r < 4; r++)
#pragma unroll
            for (int o = 0; o < 6; o++) acc2[r][o] = 0ull;
#pragma unroll
        for (int c = 0; c < 2; c++) {
            const int m0 = c * 128 + (lane << 2);
#pragma unroll
            for (int o = 0; o < 6; o++) {
                ulonglong2 vv = *reinterpret_cast<const ulonglong2*>(&S.VT[o][m0]);
#pragma unroll
                for (int r = 0; r < 4; r++) {
                    acc2[r][o] = fma2_(s2[c][r][0], vv.x, acc2[r][o]);
                    acc2[r][o] = fma2_(s2[c][r][1], vv.y, acc2[r][o]);
                }
            }
        }
        float inv[4];
        {
            float s0, s1, s2_, s3;
            upk2(d01, s0, s1); upk2(d23, s2_, s3);
            inv[0] = __frcp_rn(s0); inv[1] = __frcp_rn(s1);
            inv[2] = __frcp_rn(s2_); inv[3] = __frcp_rn(s3);
        }
        u64 inv2[4];
#pragma unroll
        for (int r = 0; r < 4; r++) inv2[r] = pk2(inv[r], inv[r]);
#pragma unroll
        for (int r = 0; r < 4; r++) {
#pragma unroll
            for (int p = 0; p < 3; p++) {
                float a0, b0, a1_, b1_;
                upk2(acc2[r][2 * p], a0, b0);
                upk2(acc2[r][2 * p + 1], a1_, b1_);
                u64 t = warp_sum2(mul2_(pk2(a0 + b0, a1_ + b1_), inv2[r]));
                if (lane == 0) {
                    float v0, v1; upk2(t, v0, v1);
                    out[((unsigned long long)bw * F_ + 2 * p) * N_ + row0 + r]     = v0;
                    out[((unsigned long long)bw * F_ + 2 * p + 1) * N_ + row0 + r] = v1;
                }
            }
        }
        // write normalized attn2 (streaming)
        if (wA) {
#pragma unroll
            for (int c = 0; c < 2; c++) {
                const int m0 = c * 128 + (lane << 2);
#pragma unroll
                for (int r = 0; r < 4; r++) {
                    stcs2(&a2[(row0 + r) * N_ + m0],
                          mul2_(s2[c][r][0], inv2[r]),
                          mul2_(s2[c][r][1], inv2[r]));
                }
            }
        }
        // ---- group 1: outputs 6..11 ----
#pragma unroll
        for (int r = 0; r < 4; r++)
#pragma unroll
            for (int o = 0; o < 6; o++) acc2[r][o] = 0ull;
#pragma unroll
        for (int c = 0; c < 2; c++) {
            const int m0 = c * 128 + (lane << 2);
#pragma unroll
            for (int o = 0; o < 6; o++) {
                ulonglong2 vv = *reinterpret_cast<const ulonglong2*>(&S.VT[6 + o][m0]);
#pragma unroll
                for (int r = 0; r < 4; r++) {
                    acc2[r][o] = fma2_(s2[c][r][0], vv.x, acc2[r][o]);
                    acc2[r][o] = fma2_(s2[c][r][1], vv.y, acc2[r][o]);
                }
            }
        }
#pragma unroll
        for (int r = 0; r < 4; r++) {
#pragma unroll
            for (int p = 0; p < 3; p++) {
                float a0, b0, a1_, b1_;
                upk2(acc2[r][2 * p], a0, b0);
                upk2(acc2[r][2 * p + 1], a1_, b1_);
                u64 t = warp_sum2(mul2_(pk2(a0 + b0, a1_ + b1_), inv2[r]));
                if (lane == 0) {
                    float v0, v1; upk2(t, v0, v1);
                    out[((unsigned long long)bw * F_ + 6 + 2 * p) * N_ + row0 + r]     = v0;
                    out[((unsigned long long)bw * F_ + 6 + 2 * p + 1) * N_ + row0 + r] = v1;
                }
            }
        }
    }
}

// ---------------------------------------------------------------------------
extern "C" void kernel_launch(void* const* d_in, const int* in_sizes, int n_in,
                              void* d_out, int out_size) {
    const float* inp  = (const float*)d_in[0];
    const int*   mask = (const int*)  d_in[1];
    const float* Wa1  = (const float*)d_in[2];
    const float* Wv1  = (const float*)d_in[3];
    const float* Wa2  = (const float*)d_in[4];
    const float* Wv2  = (const float*)d_in[5];
    float* out = (float*)d_out;

    const int wA = (out_size >= (int)(OFF_A2 + (unsigned long long)BW_ * N_ * N_)) ? 1 : 0;
    const int wW = (out_size >= (int)TOT_FULL) ? 1 : 0;

    cudaFuncSetAttribute(spatial_attn_kernel,
                         cudaFuncAttributeMaxDynamicSharedMemorySize,
                         (int)sizeof(Smem));

    pack_mask_kernel<<<N_, 256>>>(mask, Wv1, Wv2, out, wW);
    spatial_attn_kernel<<<BW_, 256, sizeof(Smem)>>>(inp, Wa1, Wv1, Wa2, Wv2, out, wA);
}